// round 8
// baseline (speedup 1.0000x reference)
#include <cuda_runtime.h>
#include <cuda_bf16.h>
#include <cstdint>

#define T_STEPS 2048
#define BATCH   16
#define DIM     1024
#define NDIM    64
#define NTOT    256
#define MROWS   (T_STEPS * BATCH)   // 32768

// ---------------- static device scratch ----------------
__device__ __nv_bfloat16 g_Ah[MROWS * DIM];
__device__ __nv_bfloat16 g_Al[MROWS * DIM];
__device__ __nv_bfloat16 g_Bh[NTOT * DIM];    // [n][k]
__device__ __nv_bfloat16 g_Bl[NTOT * DIM];
__device__ float g_P[MROWS * NTOT];           // [t*B+b][k|v|q|a]
__device__ float4 g_CE4[MROWS];               // (KK1, KK2, E0, E1) per (t,b)

// ---------------- PTX helpers (baseline ISA only) ----------------
__device__ __forceinline__ uint32_t smem_u32(const void* p) {
    return (uint32_t)__cvta_generic_to_shared(p);
}
__device__ __forceinline__ void cpa16(uint32_t sa, const void* g) {
    asm volatile("cp.async.cg.shared.global [%0], [%1], 16;" :: "r"(sa), "l"(g) : "memory");
}
__device__ __forceinline__ void cp_commit() {
    asm volatile("cp.async.commit_group;" ::: "memory");
}
template<int N>
__device__ __forceinline__ void cp_wait() {
    asm volatile("cp.async.wait_group %0;" :: "n"(N) : "memory");
}
__device__ __forceinline__ void ldm_x4(uint32_t& r0, uint32_t& r1, uint32_t& r2, uint32_t& r3,
                                       uint32_t addr) {
    asm volatile("ldmatrix.sync.aligned.m8n8.x4.shared.b16 {%0,%1,%2,%3}, [%4];"
                 : "=r"(r0), "=r"(r1), "=r"(r2), "=r"(r3) : "r"(addr));
}
__device__ __forceinline__ void mma_bf16(float* c, const uint32_t* a, const uint32_t* b) {
    asm volatile("mma.sync.aligned.m16n8k16.row.col.f32.bf16.bf16.f32 "
                 "{%0,%1,%2,%3}, {%4,%5,%6,%7}, {%8,%9}, {%0,%1,%2,%3};"
                 : "+f"(c[0]), "+f"(c[1]), "+f"(c[2]), "+f"(c[3])
                 : "r"(a[0]), "r"(a[1]), "r"(a[2]), "r"(a[3]), "r"(b[0]), "r"(b[1]));
}

__device__ __forceinline__ void split_bf16(float x, __nv_bfloat16& h, __nv_bfloat16& l) {
    h = __float2bfloat16(x);
    l = __float2bfloat16(x - __bfloat162float(h));
}

// ---------------- prep kernels ----------------
__global__ void convert_x(const float* __restrict__ x) {
    const int total4 = MROWS * DIM / 4;
    for (int i = blockIdx.x * blockDim.x + threadIdx.x; i < total4;
         i += gridDim.x * blockDim.x) {
        float4 v = ((const float4*)x)[i];
        __nv_bfloat16 h0, h1, h2, h3, l0, l1, l2, l3;
        split_bf16(v.x, h0, l0); split_bf16(v.y, h1, l1);
        split_bf16(v.z, h2, l2); split_bf16(v.w, h3, l3);
        ((__nv_bfloat162*)g_Ah)[2 * i + 0] = __nv_bfloat162(h0, h1);
        ((__nv_bfloat162*)g_Ah)[2 * i + 1] = __nv_bfloat162(h2, h3);
        ((__nv_bfloat162*)g_Al)[2 * i + 0] = __nv_bfloat162(l0, l1);
        ((__nv_bfloat162*)g_Al)[2 * i + 1] = __nv_bfloat162(l2, l3);
    }
}

__global__ void convert_w(const float* __restrict__ Wk, const float* __restrict__ Wv,
                          const float* __restrict__ Wq, const float* __restrict__ Wa) {
    int n = blockIdx.x;
    int g = n >> 6, r = n & 63;
    const float* W = (g == 0) ? Wk : (g == 1) ? Wv : (g == 2) ? Wq : Wa;
    for (int d = threadIdx.x; d < DIM; d += blockDim.x) {
        __nv_bfloat16 h, l;
        split_bf16(W[r * DIM + d], h, l);
        g_Bh[n * DIM + d] = h;
        g_Bl[n * DIM + d] = l;
    }
}

// ---------------- mma.sync GEMM (unchanged) ----------------
#define BM 128
#define BN 128
#define BK 32
#define LDP 40
#define KT (DIM / BK)
#define NSTAGE 3
#define STAGE_ELE (4 * 128 * LDP)

__device__ __forceinline__ uint32_t soff(int stage, int arr, int row, int col) {
    return (uint32_t)(((stage * STAGE_ELE) + ((arr * 128 + row) * LDP) + col) * 2);
}

__global__ __launch_bounds__(256, 1) void gemm_mma(int unused) {
    extern __shared__ __nv_bfloat16 smem[];
    const uint32_t sbase = smem_u32(smem);

    const int m0 = blockIdx.y * BM;
    const int n0 = blockIdx.x * BN;
    const int tid = threadIdx.x;
    const int wid = tid >> 5;
    const int lane = tid & 31;
    const int warp_m = (wid & 3) * 32;
    const int warp_n = (wid >> 2) * 64;

    float acc[2][8][4];
    #pragma unroll
    for (int i = 0; i < 2; i++)
        #pragma unroll
        for (int j = 0; j < 8; j++)
            #pragma unroll
            for (int r = 0; r < 4; r++) acc[i][j][r] = 0.f;

    const int lm = lane >> 3;
    const int arow = (lm & 1) * 8 + (lane & 7);
    const int akc  = (lm >> 1) * 8;
    const int bnof = (lm >> 1) * 8 + (lane & 7);
    const int bkc  = (lm & 1) * 8;

    auto load_stage = [&](int stage, int kt) {
        const int k0 = kt * BK;
        #pragma unroll
        for (int arr = 0; arr < 4; arr++) {
            const __nv_bfloat16* gb = (arr == 0) ? g_Ah : (arr == 1) ? g_Al
                                   : (arr == 2) ? g_Bh : g_Bl;
            const int rbase = (arr < 2) ? m0 : n0;
            #pragma unroll
            for (int h = 0; h < 2; h++) {
                int cl = h * 256 + tid;
                int row = cl >> 2;
                int seg = cl & 3;
                cpa16(sbase + soff(stage, arr, row, seg * 8),
                      gb + (size_t)(rbase + row) * DIM + k0 + seg * 8);
            }
        }
        cp_commit();
    };

    load_stage(0, 0);
    load_stage(1, 1);

    int cur = 0;
    for (int kt = 0; kt < KT; ++kt) {
        if (kt + 2 < KT) {
            load_stage((kt + 2) % NSTAGE, kt + 2);
            cp_wait<2>();
        } else if (kt + 1 < KT) {
            cp_wait<1>();
        } else {
            cp_wait<0>();
        }
        __syncthreads();

        #pragma unroll
        for (int kk = 0; kk < BK; kk += 16) {
            uint32_t ah[2][4], al[2][4], bh[8][2], bl[8][2];
            #pragma unroll
            for (int mi = 0; mi < 2; mi++) {
                ldm_x4(ah[mi][0], ah[mi][1], ah[mi][2], ah[mi][3],
                       sbase + soff(cur, 0, warp_m + mi * 16 + arow, kk + akc));
                ldm_x4(al[mi][0], al[mi][1], al[mi][2], al[mi][3],
                       sbase + soff(cur, 1, warp_m + mi * 16 + arow, kk + akc));
            }
            #pragma unroll
            for (int p = 0; p < 4; p++) {
                ldm_x4(bh[2 * p][0], bh[2 * p][1], bh[2 * p + 1][0], bh[2 * p + 1][1],
                       sbase + soff(cur, 2, warp_n + p * 16 + bnof, kk + bkc));
                ldm_x4(bl[2 * p][0], bl[2 * p][1], bl[2 * p + 1][0], bl[2 * p + 1][1],
                       sbase + soff(cur, 3, warp_n + p * 16 + bnof, kk + bkc));
            }
            #pragma unroll
            for (int mi = 0; mi < 2; mi++)
                #pragma unroll
                for (int nb = 0; nb < 8; nb++) {
                    mma_bf16(acc[mi][nb], ah[mi], bh[nb]);
                    mma_bf16(acc[mi][nb], ah[mi], bl[nb]);
                    mma_bf16(acc[mi][nb], al[mi], bh[nb]);
                }
        }
        __syncthreads();
        cur = (cur + 1) % NSTAGE;
    }

    const int cr = lane >> 2;
    const int cc = (lane & 3) * 2;
    #pragma unroll
    for (int mi = 0; mi < 2; mi++) {
        #pragma unroll
        for (int nb = 0; nb < 8; nb++) {
            int row = m0 + warp_m + mi * 16 + cr;
            int col = n0 + warp_n + nb * 8 + cc;
            *(float2*)&g_P[(size_t)row * NTOT + col] =
                make_float2(acc[mi][nb][0], acc[mi][nb][1]);
            *(float2*)&g_P[(size_t)(row + 8) * NTOT + col] =
                make_float2(acc[mi][nb][2], acc[mi][nb][3]);
        }
    }
}

// ---------------- parallel cross-step dots ----------------
// KK1_t = k_{t-1}.k_t, KK2_t = k_{t-2}.k_t, E0_t = k_t.q_t, E1_t = k_{t-1}.q_t
__global__ __launch_bounds__(256) void kq_dots4() {
    const int widx = (blockIdx.x * blockDim.x + threadIdx.x) >> 5;   // t*B+b
    if (widx >= MROWS) return;
    const int lane = threadIdx.x & 31;
    const int t = widx / BATCH;

    const float* p = g_P + (size_t)widx * NTOT;
    float2 kt = *(const float2*)&p[2 * lane];
    float2 qt = *(const float2*)&p[2 * NDIM + 2 * lane];
    float e0 = fmaf(kt.x, qt.x, kt.y * qt.y);
    float kk1 = 0.f, kk2 = 0.f, e1 = 0.f;
    if (t > 0) {
        const float* pm = g_P + (size_t)(widx - BATCH) * NTOT;
        float2 km = *(const float2*)&pm[2 * lane];
        kk1 = fmaf(km.x, kt.x, km.y * kt.y);
        e1  = fmaf(km.x, qt.x, km.y * qt.y);
    }
    if (t > 1) {
        const float* pm2 = g_P + (size_t)(widx - 2 * BATCH) * NTOT;
        float2 km2 = *(const float2*)&pm2[2 * lane];
        kk2 = fmaf(km2.x, kt.x, km2.y * kt.y);
    }
    #pragma unroll
    for (int o = 1; o < 32; o <<= 1) {
        kk1 += __shfl_xor_sync(0xffffffffu, kk1, o);
        kk2 += __shfl_xor_sync(0xffffffffu, kk2, o);
        e0  += __shfl_xor_sync(0xffffffffu, e0, o);
        e1  += __shfl_xor_sync(0xffffffffu, e1, o);
    }
    if (lane == 0) g_CE4[widx] = make_float4(kk1, kk2, e0, e1);
}

// ---------------- recurrence: double-deferred dots, register-only serial chain ----------------
// r1_t    = a_{t-1}*inner_t + w_{t-1}*KK1_t ; inner_t = a_{t-2}*U_t + w_{t-2}*KK2_t
// U_t     = S_{t-3}.k_t  (computed at iter t-2, >=1.5 steps of slack)
// R2_t    = a_{t-1}*V_t + w_{t-1}*E1_t ; V_t = S_{t-2}.q_t (computed at iter t-1)
// out_t   = silu-gate(a_t*R2_t + w_t*E0_t)
#define RDEPTH 8

__device__ __forceinline__ float red8(float x) {
    x += __shfl_xor_sync(0xffffffffu, x, 1);
    x += __shfl_xor_sync(0xffffffffu, x, 2);
    x += __shfl_xor_sync(0xffffffffu, x, 4);
    return x;
}
__device__ __forceinline__ float dot8f(const float* S, const float4 a, const float4 b) {
    float p = fmaf(S[0], a.x, S[4] * b.x);
    float q = fmaf(S[1], a.y, S[5] * b.y);
    p = fmaf(S[2], a.z, p);
    q = fmaf(S[6], b.z, q);
    p = fmaf(S[3], a.w, p);
    q = fmaf(S[7], b.w, q);
    return p + q;
}

__global__ __launch_bounds__(32, 1) void recur_w(const float* __restrict__ S0,
                                                 const float* __restrict__ dalpha,
                                                 const float* __restrict__ balpha,
                                                 float* __restrict__ out,
                                                 float* __restrict__ Sfinal) {
    const int b = blockIdx.x >> 4;           // batch
    const int rw = (blockIdx.x & 15) * 4;    // first row of this warp
    const int lane = threadIdx.x;
    const int row = rw + (lane >> 3);        // global row (0..63)
    const int c = lane & 7;                  // col chunk: cols [c*8, c*8+8)

    __shared__ __align__(16) float ring[RDEPTH][NTOT];
    __shared__ __align__(16) float4 ringCE[RDEPTH];

    float S[8];
    {
        const float* sp = S0 + ((size_t)b * NDIM + row) * NDIM + c * 8;
        float4 v0 = *(const float4*)(sp);
        float4 v1 = *(const float4*)(sp + 4);
        S[0] = v0.x; S[1] = v0.y; S[2] = v0.z; S[3] = v0.w;
        S[4] = v1.x; S[5] = v1.y; S[6] = v1.z; S[7] = v1.w;
    }
    const float da = dalpha[row];
    const float ba = balpha[row];

    // prime ring stages 0..6 (7 groups)
    #pragma unroll
    for (int p = 0; p < 7; p++) {
        const float* gp = g_P + (size_t)(p * BATCH + b) * NTOT;
        uint32_t sa = smem_u32(&ring[p][lane * 8]);
        cpa16(sa, gp + lane * 8);
        cpa16(sa + 16, gp + lane * 8 + 4);
        if (lane == 0) cpa16(smem_u32(&ringCE[p]), &g_CE4[p * BATCH + b]);
        cp_commit();
    }
    cp_wait<5>();      // slots 0,1 ready
    __syncwarp();

    // prologue: U_0 = S0.k_0, U_1 = S0.k_1, V_0 = S0.q_0
    float Uc, Ua, Vc;
    {
        float4 k0a = *(const float4*)&ring[0][c * 8];
        float4 k0b = *(const float4*)&ring[0][c * 8 + 4];
        float4 k1a = *(const float4*)&ring[1][c * 8];
        float4 k1b = *(const float4*)&ring[1][c * 8 + 4];
        float4 q0a = *(const float4*)&ring[0][2 * NDIM + c * 8];
        float4 q0b = *(const float4*)&ring[0][2 * NDIM + c * 8 + 4];
        Uc = red8(dot8f(S, k0a, k0b));
        Ua = red8(dot8f(S, k1a, k1b));
        Vc = red8(dot8f(S, q0a, q0b));
    }
    float4 CEc = ringCE[0];
    float az = ring[0][3 * NDIM + row] + ba;
    float inner = Uc;            // inner_0 = 1*U_0 + 0
    float ap1 = 1.f, wp1 = 0.f;

    for (int t = 0; t < T_STEPS; ++t) {
        cp_wait<4>();
        __syncwarp();

        const int s0 = t & (RDEPTH - 1);
        const int s1 = (t + 1) & (RDEPTH - 1);
        const int s2 = (t + 2) & (RDEPTH - 1);

        // loads (all off-chain)
        const float4 kta = *(const float4*)&ring[s0][c * 8];
        const float4 ktb = *(const float4*)&ring[s0][c * 8 + 4];
        const float vt = ring[s0][NDIM + row];
        const float4 kpa = *(const float4*)&ring[s2][c * 8];
        const float4 kpb = *(const float4*)&ring[s2][c * 8 + 4];
        const float4 qna = *(const float4*)&ring[s1][2 * NDIM + c * 8];
        const float4 qnb = *(const float4*)&ring[s1][2 * NDIM + c * 8 + 4];
        const float an = ring[s1][3 * NDIM + row];
        const float4 CEn = ringCE[s1];

        // off-chain scalar pre-compute (uses old ap1/wp1)
        const float R2 = fmaf(ap1, Vc, wp1 * CEc.w);        // a_{t-1}V_t + w_{t-1}E1_t
        const float inner_n = fmaf(ap1, Ua, wp1 * CEn.y);   // inner_{t+1}

        // ---- serial chain ----
        const float r1 = fmaf(ap1, inner, wp1 * CEc.x);
        const float z = fmaf(da, r1, az);
        const float e = __expf(-z);
        const float alpha = __fdividef(1.0f, 1.0f + e);
        const float w = fmaf(-vt, alpha, vt);               // (1-alpha)*v

        // ---- output (off-chain) ----
        const float o = fmaf(alpha, R2, w * CEc.z);
        const float eo = __expf(-o);
        const float res = o * o * __fdividef(1.0f, 1.0f + eo);
        if (c == 0)
            out[((size_t)t * BATCH + b) * NDIM + row] = res;

        // ---- dots with pre-update S = S_{t-1} (slack >= 1 step) ----
        const float Un = red8(dot8f(S, kpa, kpb));   // U_{t+2} = S_{t-1}.k_{t+2}
        const float Vn = red8(dot8f(S, qna, qnb));   // V_{t+1} = S_{t-1}.q_{t+1}

        // ---- S update ----
        S[0] = fmaf(alpha, S[0], w * kta.x);
        S[1] = fmaf(alpha, S[1], w * kta.y);
        S[2] = fmaf(alpha, S[2], w * kta.z);
        S[3] = fmaf(alpha, S[3], w * kta.w);
        S[4] = fmaf(alpha, S[4], w * ktb.x);
        S[5] = fmaf(alpha, S[5], w * ktb.y);
        S[6] = fmaf(alpha, S[6], w * ktb.z);
        S[7] = fmaf(alpha, S[7], w * ktb.w);

        // ---- prefetch stage t+7 ----
        {
            const int tp = t + 7;
            if (tp < T_STEPS) {
                const float* gp = g_P + (size_t)(tp * BATCH + b) * NTOT;
                uint32_t sa = smem_u32(&ring[tp & (RDEPTH - 1)][lane * 8]);
                cpa16(sa, gp + lane * 8);
                cpa16(sa + 16, gp + lane * 8 + 4);
                if (lane == 0)
                    cpa16(smem_u32(&ringCE[tp & (RDEPTH - 1)]), &g_CE4[tp * BATCH + b]);
            }
            cp_commit();
        }

        // ---- rotate (registers only) ----
        inner = inner_n;
        Uc = Ua; Ua = Un;
        Vc = Vn;
        CEc = CEn;
        az = an + ba;
        ap1 = alpha; wp1 = w;
    }

    if (Sfinal != nullptr) {
        float* sp = Sfinal + ((size_t)b * NDIM + row) * NDIM + c * 8;
        *(float4*)(sp) = make_float4(S[0], S[1], S[2], S[3]);
        *(float4*)(sp + 4) = make_float4(S[4], S[5], S[6], S[7]);
    }
}

// ---------------- launch ----------------
extern "C" void kernel_launch(void* const* d_in, const int* in_sizes, int n_in,
                              void* d_out, int out_size) {
    const float* x  = (const float*)d_in[0];
    const float* S0 = (const float*)d_in[1];
    const float* Wk = (const float*)d_in[2];
    const float* Wv = (const float*)d_in[3];
    const float* Wq = (const float*)d_in[4];
    const float* Wa = (const float*)d_in[5];
    const float* da = (const float*)d_in[6];
    const float* ba = (const float*)d_in[7];

    float* out = (float*)d_out;
    const int out_elems = T_STEPS * BATCH * NDIM;
    const int sf_elems  = BATCH * NDIM * NDIM;
    float* Sf = (out_size >= out_elems + sf_elems) ? (out + out_elems) : nullptr;

    const int smem_bytes = NSTAGE * STAGE_ELE * 2;   // 122880
    cudaFuncSetAttribute(gemm_mma, cudaFuncAttributeMaxDynamicSharedMemorySize, smem_bytes);

    convert_x<<<2048, 256>>>(x);
    convert_w<<<NTOT, 256>>>(Wk, Wv, Wq, Wa);

    dim3 ggrid(NTOT / BN, MROWS / BM);   // (2, 256)
    gemm_mma<<<ggrid, 256, smem_bytes>>>(0);

    kq_dots4<<<MROWS / 8, 256>>>();
    recur_w<<<BATCH * 16, 32>>>(S0, da, ba, out, Sf);
}